// round 1
// baseline (speedup 1.0000x reference)
#include <cuda_runtime.h>
#include <math.h>

#define EPSY 0.1f
#define B_  64
#define P_  196
#define C_  768
#define TM_ 384
#define CM_ 3072

// ---------------- scratch (__device__ globals; no allocation allowed) ----------------
__device__ float g_H1[(size_t)B_ * C_ * TM_];   // (49152, 384)
__device__ float g_X1[(size_t)B_ * P_ * C_];    // (B,P,C) after token mixing
__device__ float g_H3[(size_t)B_ * P_ * CM_];   // (12544, 3072)
__device__ float g_twT[P_ * TM_];               // (196, 384)
__device__ float g_w2T[TM_ * P_];               // (384, 196)
__device__ float g_cwT[C_ * CM_];               // (768, 3072)
__device__ float g_w4T[CM_ * C_];               // (3072, 768)
__device__ float g_twn[TM_];
__device__ float g_cwn[CM_];
__device__ float g_xn1[B_ * C_];                // ||x_t row||^2 per (b,c)
__device__ float g_xn2[B_ * P_];                // ||x1 row||^2 per (b,p)
__device__ float g_scales[2];

// ---------------- prep kernels ----------------

// out[C x R] = in[R x C]^T
__global__ void transpose_k(const float* __restrict__ in, float* __restrict__ out,
                            int R, int C) {
    __shared__ float tile[32][33];
    int c0 = blockIdx.x * 32, r0 = blockIdx.y * 32;
    int c = c0 + threadIdx.x;
    #pragma unroll
    for (int i = 0; i < 32; i += 8) {
        int r = r0 + threadIdx.y + i;
        if (r < R && c < C) tile[threadIdx.y + i][threadIdx.x] = in[(size_t)r * C + c];
    }
    __syncthreads();
    int oc = r0 + threadIdx.x;           // column of out = original row
    #pragma unroll
    for (int i = 0; i < 32; i += 8) {
        int orow = c0 + threadIdx.y + i; // row of out = original col
        if (orow < C && oc < R) out[(size_t)orow * R + oc] = tile[threadIdx.x][threadIdx.y + i];
    }
}

// row-wise sum of squares: in (M x K) row-major -> out[M]
__global__ void rownorm_k(const float* __restrict__ in, float* __restrict__ out,
                          int M, int K) {
    int row = blockIdx.x * 8 + (threadIdx.x >> 5);
    int lane = threadIdx.x & 31;
    if (row >= M) return;
    const float* p = in + (size_t)row * K;
    float s = 0.f;
    for (int k = lane; k < K; k += 32) { float v = p[k]; s += v * v; }
    #pragma unroll
    for (int o = 16; o; o >>= 1) s += __shfl_xor_sync(0xffffffffu, s, o);
    if (lane == 0) out[row] = s;
}

// xn1[b*C + c] = sum_p x[b][p][c]^2
__global__ void xnorm_token_k(const float* __restrict__ x, float* __restrict__ out) {
    int idx = blockIdx.x * blockDim.x + threadIdx.x;
    if (idx >= B_ * C_) return;
    int b = idx / C_, c = idx % C_;
    const float* p = x + (size_t)b * P_ * C_ + c;
    float s = 0.f;
    #pragma unroll 4
    for (int k = 0; k < P_; k++) { float v = p[(size_t)k * C_]; s += v * v; }
    out[idx] = s;
}

__global__ void scales_k(const float* __restrict__ ta, const float* __restrict__ ca,
                         float* __restrict__ out) {
    if (threadIdx.x == 0) {
        float bt = (float)((double)TM_ / log((double)TM_ + 1.0));
        float bc = (float)((double)CM_ / log((double)CM_ + 1.0));
        out[0] = powf(sqrtf(bt), ta[0]);
        out[1] = powf(sqrtf(bc), ca[0]);
    }
}

// ---------------- main GEMM with fused epilogues ----------------
// Computes acc[r][n] = sum_k A[r][k] * Bt[k][n]   (Bt is K x N row-major)
//
// AMODE_ROW : A is M x K row-major
// AMODE_TOKX: A[r][k] = x[b*P*C + k*C + c], r = b*C + c   (logical transpose of x)
// EPI_YAT   : Out[r*N+n] = scale * (acc+bias[n])^2 / (wn[n]+xn[r]-2*acc+EPS)
// EPI_SCAT  : Out[b*P*C + n*C + c] = shortcut[same] + acc + bias[n], r=b*C+c  (n<N guard)
// EPI_ROW   : Out[r*N+n] = shortcut[r*N+n] + acc + bias[n]

#define AMODE_ROW  0
#define AMODE_TOKX 1
#define EPI_YAT  0
#define EPI_SCAT 1
#define EPI_ROW  2

template <int AMODE, int EPI>
__global__ __launch_bounds__(256, 2)
void gemm_k(const float* __restrict__ A, const float* __restrict__ Bt,
            float* __restrict__ Out, int M, int N, int K,
            const float* __restrict__ bias,
            const float* __restrict__ wn, const float* __restrict__ xn,
            const float* __restrict__ scales, int scale_idx,
            const float* __restrict__ shortcut) {
    constexpr int BM = 128, BN = 128, BK = 8;
    __shared__ float As[BK][BM + 4];
    __shared__ float Bs[BK][BN];

    const int r0 = blockIdx.y * BM;
    const int n0 = blockIdx.x * BN;
    const int t  = threadIdx.x;
    const int tx = t & 15;       // 16 cols of threads, 8 outputs each
    const int ty = t >> 4;       // 16 rows of threads, 8 outputs each

    float acc[8][8];
    #pragma unroll
    for (int i = 0; i < 8; i++)
        #pragma unroll
        for (int j = 0; j < 8; j++) acc[i][j] = 0.f;

    const float* Ablk = A;
    if (AMODE == AMODE_TOKX) {
        int b  = r0 / C_;
        int c0 = r0 % C_;                       // 128 | 768, so one b per block
        Ablk = A + (size_t)b * P_ * C_ + c0;    // elem (rloc,k) = Ablk[rloc + k*C_]
    }

    for (int k0 = 0; k0 < K; k0 += BK) {
        // ---- load A tile into As[k][r] ----
        #pragma unroll
        for (int i = 0; i < 4; i++) {
            int idx = t + i * 256;
            if (AMODE == AMODE_ROW) {
                int k = idx & (BK - 1), r = idx >> 3;
                float v = 0.f;
                if (k0 + k < K) v = A[(size_t)(r0 + r) * K + k0 + k];
                As[k][r] = v;
            } else {
                int r = idx & (BM - 1), k = idx >> 7;
                float v = 0.f;
                if (k0 + k < K) v = Ablk[r + (size_t)(k0 + k) * C_];
                As[k][r] = v;
            }
        }
        // ---- load B tile into Bs[k][n] (Bt row-major, coalesced) ----
        #pragma unroll
        for (int i = 0; i < 4; i++) {
            int idx = t + i * 256;
            int n = idx & (BN - 1), k = idx >> 7;
            float v = 0.f;
            if ((k0 + k) < K && (n0 + n) < N) v = Bt[(size_t)(k0 + k) * N + n0 + n];
            Bs[k][n] = v;
        }
        __syncthreads();

        #pragma unroll
        for (int k = 0; k < BK; k++) {
            float a[8], b[8];
            #pragma unroll
            for (int i = 0; i < 8; i++) a[i] = As[k][ty * 8 + i];
            #pragma unroll
            for (int j = 0; j < 8; j++) b[j] = Bs[k][tx * 8 + j];
            #pragma unroll
            for (int i = 0; i < 8; i++)
                #pragma unroll
                for (int j = 0; j < 8; j++)
                    acc[i][j] = fmaf(a[i], b[j], acc[i][j]);
        }
        __syncthreads();
    }

    // ---- epilogue ----
    const float scale = (EPI == EPI_YAT) ? scales[scale_idx] : 0.f;
    #pragma unroll
    for (int i = 0; i < 8; i++) {
        const int r = r0 + ty * 8 + i;
        const float xnr = (EPI == EPI_YAT) ? xn[r] : 0.f;
        #pragma unroll
        for (int j = 0; j < 8; j++) {
            const int n = n0 + tx * 8 + j;
            if (n >= N) continue;
            const float d = acc[i][j];
            if (EPI == EPI_YAT) {
                float dot  = d + bias[n];
                float dist = wn[n] + xnr - 2.f * d + EPSY;
                Out[(size_t)r * N + n] = scale * dot * dot / dist;
            } else if (EPI == EPI_ROW) {
                size_t o = (size_t)r * N + n;
                Out[o] = shortcut[o] + d + bias[n];
            } else { // EPI_SCAT
                int b = r / C_, c = r % C_;
                size_t o = (size_t)b * P_ * C_ + (size_t)n * C_ + c;
                Out[o] = shortcut[o] + d + bias[n];
            }
        }
    }
}

// ---------------- launch ----------------
extern "C" void kernel_launch(void* const* d_in, const int* in_sizes, int n_in,
                              void* d_out, int out_size) {
    const float* x  = (const float*)d_in[0];
    const float* tw = (const float*)d_in[1];
    const float* tb = (const float*)d_in[2];
    const float* ta = (const float*)d_in[3];
    const float* w2 = (const float*)d_in[4];
    const float* b2 = (const float*)d_in[5];
    const float* cw = (const float*)d_in[6];
    const float* cb = (const float*)d_in[7];
    const float* ca = (const float*)d_in[8];
    const float* w4 = (const float*)d_in[9];
    const float* b4 = (const float*)d_in[10];
    float* out = (float*)d_out;

    float *H1, *X1, *H3, *twT, *w2T, *cwT, *w4T, *twn, *cwn, *xn1, *xn2, *scl;
    cudaGetSymbolAddress((void**)&H1,  g_H1);
    cudaGetSymbolAddress((void**)&X1,  g_X1);
    cudaGetSymbolAddress((void**)&H3,  g_H3);
    cudaGetSymbolAddress((void**)&twT, g_twT);
    cudaGetSymbolAddress((void**)&w2T, g_w2T);
    cudaGetSymbolAddress((void**)&cwT, g_cwT);
    cudaGetSymbolAddress((void**)&w4T, g_w4T);
    cudaGetSymbolAddress((void**)&twn, g_twn);
    cudaGetSymbolAddress((void**)&cwn, g_cwn);
    cudaGetSymbolAddress((void**)&xn1, g_xn1);
    cudaGetSymbolAddress((void**)&xn2, g_xn2);
    cudaGetSymbolAddress((void**)&scl, g_scales);

    dim3 tb32(32, 8);
    // weight transposes
    transpose_k<<<dim3((P_  + 31) / 32, (TM_ + 31) / 32), tb32>>>(tw, twT, TM_, P_);
    transpose_k<<<dim3((TM_ + 31) / 32, (P_  + 31) / 32), tb32>>>(w2, w2T, P_,  TM_);
    transpose_k<<<dim3((C_  + 31) / 32, (CM_ + 31) / 32), tb32>>>(cw, cwT, CM_, C_);
    transpose_k<<<dim3((CM_ + 31) / 32, (C_  + 31) / 32), tb32>>>(w4, w4T, C_,  CM_);
    // weight norms + scales + x token norms
    rownorm_k<<<(TM_ + 7) / 8, 256>>>(tw, twn, TM_, P_);
    rownorm_k<<<(CM_ + 7) / 8, 256>>>(cw, cwn, CM_, C_);
    xnorm_token_k<<<(B_ * C_ + 255) / 256, 256>>>(x, xn1);
    scales_k<<<1, 32>>>(ta, ca, scl);

    const int M1 = B_ * C_;   // 49152
    const int M3 = B_ * P_;   // 12544

    // GEMM1 + YAT (token): H1 (M1 x TM_)
    gemm_k<AMODE_TOKX, EPI_YAT><<<dim3(TM_ / 128, M1 / 128), 256>>>(
        x, twT, H1, M1, TM_, P_, tb, twn, xn1, scl, 0, nullptr);

    // GEMM2 + residual scatter: X1 (B,P,C)
    gemm_k<AMODE_ROW, EPI_SCAT><<<dim3((P_ + 127) / 128, M1 / 128), 256>>>(
        H1, w2T, X1, M1, P_, TM_, b2, nullptr, nullptr, nullptr, 0, x);

    // norms of X1 rows (b,p)
    rownorm_k<<<(M3 + 7) / 8, 256>>>(X1, xn2, M3, C_);

    // GEMM3 + YAT (channel): H3 (M3 x CM_)
    gemm_k<AMODE_ROW, EPI_YAT><<<dim3(CM_ / 128, M3 / 128), 256>>>(
        X1, cwT, H3, M3, CM_, C_, cb, cwn, xn2, scl, 1, nullptr);

    // GEMM4 + residual: out (M3 x C_)
    gemm_k<AMODE_ROW, EPI_ROW><<<dim3(C_ / 128, M3 / 128), 256>>>(
        H3, w4T, out, M3, C_, CM_, b4, nullptr, nullptr, nullptr, 0, X1);
}

// round 3
// speedup vs baseline: 1.8829x; 1.8829x over previous
#include <cuda_runtime.h>
#include <math.h>

#define EPSY 0.1f
#define B_  64
#define P_  196
#define C_  768
#define TM_ 384
#define CM_ 3072

// ---------------- scratch ----------------
__device__ float g_H1[(size_t)B_ * C_ * TM_];
__device__ float g_X1[(size_t)B_ * P_ * C_];
__device__ float g_H3[(size_t)B_ * P_ * CM_];
__device__ float g_twT[P_ * TM_];
__device__ float g_w2T[TM_ * P_];
__device__ float g_cwT[C_ * CM_];
__device__ float g_w4T[CM_ * C_];
__device__ float g_twn[TM_];
__device__ float g_cwn[CM_];
__device__ float g_xn1[B_ * C_];
__device__ float g_xn2[B_ * P_];
__device__ float g_scales[2];

__device__ __forceinline__ unsigned f2tf(float v) {
    unsigned u;
    asm("cvt.rna.tf32.f32 %0, %1;" : "=r"(u) : "f"(v));
    return u;
}

// ---------------- prep kernels ----------------
__global__ void transpose_k(const float* __restrict__ in, float* __restrict__ out,
                            int R, int C) {
    __shared__ float tile[32][33];
    int c0 = blockIdx.x * 32, r0 = blockIdx.y * 32;
    int c = c0 + threadIdx.x;
    #pragma unroll
    for (int i = 0; i < 32; i += 8) {
        int r = r0 + threadIdx.y + i;
        if (r < R && c < C) tile[threadIdx.y + i][threadIdx.x] = in[(size_t)r * C + c];
    }
    __syncthreads();
    int oc = r0 + threadIdx.x;
    #pragma unroll
    for (int i = 0; i < 32; i += 8) {
        int orow = c0 + threadIdx.y + i;
        if (orow < C && oc < R) out[(size_t)orow * R + oc] = tile[threadIdx.x][threadIdx.y + i];
    }
}

__global__ void rownorm_k(const float* __restrict__ in, float* __restrict__ out,
                          int M, int K) {
    int row = blockIdx.x * 8 + (threadIdx.x >> 5);
    int lane = threadIdx.x & 31;
    if (row >= M) return;
    const float* p = in + (size_t)row * K;
    float s = 0.f;
    for (int k = lane; k < K; k += 32) { float v = p[k]; s += v * v; }
    #pragma unroll
    for (int o = 16; o; o >>= 1) s += __shfl_xor_sync(0xffffffffu, s, o);
    if (lane == 0) out[row] = s;
}

__global__ void xnorm_token_k(const float* __restrict__ x, float* __restrict__ out) {
    int idx = blockIdx.x * blockDim.x + threadIdx.x;
    if (idx >= B_ * C_) return;
    int b = idx / C_, c = idx % C_;
    const float* p = x + (size_t)b * P_ * C_ + c;
    float s = 0.f;
    #pragma unroll 4
    for (int k = 0; k < P_; k++) { float v = p[(size_t)k * C_]; s += v * v; }
    out[idx] = s;
}

__global__ void scales_k(const float* __restrict__ ta, const float* __restrict__ ca,
                         float* __restrict__ out) {
    if (threadIdx.x == 0) {
        float bt = (float)((double)TM_ / log((double)TM_ + 1.0));
        float bc = (float)((double)CM_ / log((double)CM_ + 1.0));
        out[0] = powf(sqrtf(bt), ta[0]);
        out[1] = powf(sqrtf(bc), ca[0]);
    }
}

// ---------------- TF32 tensor-core GEMM with fused epilogues ----------------
#define AMODE_ROW  0
#define AMODE_TOKX 1
#define EPI_YAT  0
#define EPI_SCAT 1
#define EPI_ROW  2

__device__ __forceinline__ void mma_tf32(float* c, const unsigned* a, const unsigned* b) {
    asm volatile(
        "mma.sync.aligned.m16n8k8.row.col.f32.tf32.tf32.f32 "
        "{%0,%1,%2,%3}, {%4,%5,%6,%7}, {%8,%9}, {%0,%1,%2,%3};\n"
        : "+f"(c[0]), "+f"(c[1]), "+f"(c[2]), "+f"(c[3])
        : "r"(a[0]), "r"(a[1]), "r"(a[2]), "r"(a[3]), "r"(b[0]), "r"(b[1]));
}

template <int AMODE, int EPI>
__global__ __launch_bounds__(256)
void gemm_tc(const float* __restrict__ A, const float* __restrict__ Bt,
             float* __restrict__ Out, int M, int N, int K,
             const float* __restrict__ bias,
             const float* __restrict__ wn, const float* __restrict__ xn,
             const float* __restrict__ scales, int scale_idx,
             const float* __restrict__ shortcut) {
    constexpr int BM = 128, BN = 128, BK = 16;
    constexpr int LDA = 136, LDB = 136;            // padded word strides
    __shared__ unsigned As[BK * LDA];              // As[k][r], tf32 bits
    __shared__ unsigned Bs[BK * LDB];              // Bs[k][n], tf32 bits

    const int t    = threadIdx.x;
    const int lane = t & 31;
    const int wid  = t >> 5;
    const int warp_m = wid & 3;                    // 4 warps along M (32 rows each)
    const int warp_n = wid >> 2;                   // 2 warps along N (64 cols each)
    const int g  = lane >> 2;                      // group id 0..7
    const int tg = lane & 3;                       // thread-in-group 0..3

    const int r0 = blockIdx.y * BM;
    const int n0 = blockIdx.x * BN;

    float acc[2][8][4];
    #pragma unroll
    for (int mt = 0; mt < 2; mt++)
        #pragma unroll
        for (int nt = 0; nt < 8; nt++)
            #pragma unroll
            for (int r = 0; r < 4; r++) acc[mt][nt][r] = 0.f;

    const float* Ablk = A;
    if (AMODE == AMODE_TOKX) {
        int b  = r0 / C_;
        int c0 = r0 % C_;
        Ablk = A + (size_t)b * P_ * C_ + c0;       // (rloc, k) -> Ablk[rloc + k*C_]
    }

    for (int k0 = 0; k0 < K; k0 += BK) {
        // ---- A tile -> As[k][r] ----
        if (AMODE == AMODE_ROW) {
            #pragma unroll
            for (int i = 0; i < 2; i++) {
                int task = t + i * 256;
                int r  = task >> 2;
                int kq = (task & 3) * 4;
                const float* src = A + (size_t)(r0 + r) * K + k0 + kq;
                float4 v = make_float4(0.f, 0.f, 0.f, 0.f);
                if (k0 + kq + 3 < K) v = *(const float4*)src;
                else {
                    if (k0 + kq + 0 < K) v.x = src[0];
                    if (k0 + kq + 1 < K) v.y = src[1];
                    if (k0 + kq + 2 < K) v.z = src[2];
                }
                As[(kq + 0) * LDA + r] = f2tf(v.x);
                As[(kq + 1) * LDA + r] = f2tf(v.y);
                As[(kq + 2) * LDA + r] = f2tf(v.z);
                As[(kq + 3) * LDA + r] = f2tf(v.w);
            }
        } else {
            #pragma unroll
            for (int i = 0; i < 8; i++) {
                int task = t + i * 256;
                int r = task & 127, k = task >> 7;
                float v = 0.f;
                if (k0 + k < K) v = Ablk[r + (size_t)(k0 + k) * C_];
                As[k * LDA + r] = f2tf(v);
            }
        }
        // ---- B tile -> Bs[k][n] ----
        #pragma unroll
        for (int i = 0; i < 2; i++) {
            int task = t + i * 256;
            int k  = task >> 5;
            int nq = (task & 31) * 4;
            float4 v = make_float4(0.f, 0.f, 0.f, 0.f);
            if (k0 + k < K) {
                const float* src = Bt + (size_t)(k0 + k) * N + n0 + nq;
                if (n0 + nq + 3 < N) v = *(const float4*)src;
                else {
                    if (n0 + nq + 0 < N) v.x = src[0];
                    if (n0 + nq + 1 < N) v.y = src[1];
                    if (n0 + nq + 2 < N) v.z = src[2];
                }
            }
            Bs[k * LDB + nq + 0] = f2tf(v.x);
            Bs[k * LDB + nq + 1] = f2tf(v.y);
            Bs[k * LDB + nq + 2] = f2tf(v.z);
            Bs[k * LDB + nq + 3] = f2tf(v.w);
        }
        __syncthreads();

        #pragma unroll
        for (int ks = 0; ks < 2; ks++) {
            const int kb = ks * 8;
            unsigned a[2][4];
            #pragma unroll
            for (int mt = 0; mt < 2; mt++) {
                int row = warp_m * 32 + mt * 16 + g;
                a[mt][0] = As[(kb + tg) * LDA + row];
                a[mt][1] = As[(kb + tg) * LDA + row + 8];
                a[mt][2] = As[(kb + tg + 4) * LDA + row];
                a[mt][3] = As[(kb + tg + 4) * LDA + row + 8];
            }
            unsigned b[8][2];
            #pragma unroll
            for (int nt = 0; nt < 8; nt++) {
                int col = warp_n * 64 + nt * 8 + g;
                b[nt][0] = Bs[(kb + tg) * LDB + col];
                b[nt][1] = Bs[(kb + tg + 4) * LDB + col];
            }
            #pragma unroll
            for (int mt = 0; mt < 2; mt++)
                #pragma unroll
                for (int nt = 0; nt < 8; nt++)
                    mma_tf32(acc[mt][nt], a[mt], b[nt]);
        }
        __syncthreads();
    }

    // ---- epilogue ----
    const float scale = (EPI == EPI_YAT) ? scales[scale_idx] : 0.f;
    #pragma unroll
    for (int mt = 0; mt < 2; mt++) {
        #pragma unroll
        for (int half = 0; half < 2; half++) {     // c0/c1 vs c2/c3 (row, row+8)
            const int row = r0 + warp_m * 32 + mt * 16 + g + half * 8;
            const float xnr = (EPI == EPI_YAT) ? xn[row] : 0.f;
            #pragma unroll
            for (int nt = 0; nt < 8; nt++) {
                const int col = n0 + warp_n * 64 + nt * 8 + tg * 2;
                const float d0 = acc[mt][nt][half * 2 + 0];
                const float d1 = acc[mt][nt][half * 2 + 1];
                if (EPI == EPI_YAT) {
                    if (col + 1 < N) {
                        float dot0 = d0 + bias[col];
                        float dot1 = d1 + bias[col + 1];
                        float ds0  = wn[col]     + xnr - 2.f * d0 + EPSY;
                        float ds1  = wn[col + 1] + xnr - 2.f * d1 + EPSY;
                        float2 o = make_float2(scale * dot0 * dot0 / ds0,
                                               scale * dot1 * dot1 / ds1);
                        *(float2*)(Out + (size_t)row * N + col) = o;
                    } else if (col < N) {
                        float dot0 = d0 + bias[col];
                        float ds0  = wn[col] + xnr - 2.f * d0 + EPSY;
                        Out[(size_t)row * N + col] = scale * dot0 * dot0 / ds0;
                    }
                } else if (EPI == EPI_ROW) {
                    if (col + 1 < N) {
                        size_t o = (size_t)row * N + col;
                        float2 v = make_float2(shortcut[o] + d0 + bias[col],
                                               shortcut[o + 1] + d1 + bias[col + 1]);
                        *(float2*)(Out + o) = v;
                    } else if (col < N) {
                        size_t o = (size_t)row * N + col;
                        Out[o] = shortcut[o] + d0 + bias[col];
                    }
                } else { // EPI_SCAT: row = b*C + c, write (b, col, c)
                    int b = row / C_, c = row % C_;
                    size_t base = (size_t)b * P_ * C_ + c;
                    if (col < N) {
                        size_t o = base + (size_t)col * C_;
                        Out[o] = shortcut[o] + d0 + bias[col];
                    }
                    if (col + 1 < N) {
                        size_t o = base + (size_t)(col + 1) * C_;
                        Out[o] = shortcut[o] + d1 + bias[col + 1];
                    }
                }
            }
        }
    }
}

// ---------------- launch ----------------
extern "C" void kernel_launch(void* const* d_in, const int* in_sizes, int n_in,
                              void* d_out, int out_size) {
    const float* x  = (const float*)d_in[0];
    const float* tw = (const float*)d_in[1];
    const float* tb = (const float*)d_in[2];
    const float* ta = (const float*)d_in[3];
    const float* w2 = (const float*)d_in[4];
    const float* b2 = (const float*)d_in[5];
    const float* cw = (const float*)d_in[6];
    const float* cb = (const float*)d_in[7];
    const float* ca = (const float*)d_in[8];
    const float* w4 = (const float*)d_in[9];
    const float* b4 = (const float*)d_in[10];
    float* out = (float*)d_out;

    float *H1, *X1, *H3, *twT, *w2T, *cwT, *w4T, *twn, *cwn, *xn1, *xn2, *scl;
    cudaGetSymbolAddress((void**)&H1,  g_H1);
    cudaGetSymbolAddress((void**)&X1,  g_X1);
    cudaGetSymbolAddress((void**)&H3,  g_H3);
    cudaGetSymbolAddress((void**)&twT, g_twT);
    cudaGetSymbolAddress((void**)&w2T, g_w2T);
    cudaGetSymbolAddress((void**)&cwT, g_cwT);
    cudaGetSymbolAddress((void**)&w4T, g_w4T);
    cudaGetSymbolAddress((void**)&twn, g_twn);
    cudaGetSymbolAddress((void**)&cwn, g_cwn);
    cudaGetSymbolAddress((void**)&xn1, g_xn1);
    cudaGetSymbolAddress((void**)&xn2, g_xn2);
    cudaGetSymbolAddress((void**)&scl, g_scales);

    dim3 tb32(32, 8);
    transpose_k<<<dim3((P_  + 31) / 32, (TM_ + 31) / 32), tb32>>>(tw, twT, TM_, P_);
    transpose_k<<<dim3((TM_ + 31) / 32, (P_  + 31) / 32), tb32>>>(w2, w2T, P_,  TM_);
    transpose_k<<<dim3((C_  + 31) / 32, (CM_ + 31) / 32), tb32>>>(cw, cwT, CM_, C_);
    transpose_k<<<dim3((CM_ + 31) / 32, (C_  + 31) / 32), tb32>>>(w4, w4T, C_,  CM_);
    rownorm_k<<<(TM_ + 7) / 8, 256>>>(tw, twn, TM_, P_);
    rownorm_k<<<(CM_ + 7) / 8, 256>>>(cw, cwn, CM_, C_);
    xnorm_token_k<<<(B_ * C_ + 255) / 256, 256>>>(x, xn1);
    scales_k<<<1, 32>>>(ta, ca, scl);

    const int M1 = B_ * C_;   // 49152
    const int M3 = B_ * P_;   // 12544

    // GEMM1 + YAT (token): H1 (M1 x TM_), K=196
    gemm_tc<AMODE_TOKX, EPI_YAT><<<dim3(TM_ / 128, M1 / 128), 256>>>(
        x, twT, H1, M1, TM_, P_, tb, twn, xn1, scl, 0, nullptr);

    // GEMM2 + residual scatter: X1 (B,P,C), K=384, N=196
    gemm_tc<AMODE_ROW, EPI_SCAT><<<dim3((P_ + 127) / 128, M1 / 128), 256>>>(
        H1, w2T, X1, M1, P_, TM_, b2, nullptr, nullptr, nullptr, 0, x);

    rownorm_k<<<(M3 + 7) / 8, 256>>>(X1, xn2, M3, C_);

    // GEMM3 + YAT (channel): H3 (M3 x CM_), K=768
    gemm_tc<AMODE_ROW, EPI_YAT><<<dim3(CM_ / 128, M3 / 128), 256>>>(
        X1, cwT, H3, M3, CM_, C_, cb, cwn, xn2, scl, 1, nullptr);

    // GEMM4 + residual: out (M3 x C_), K=3072
    gemm_tc<AMODE_ROW, EPI_ROW><<<dim3(C_ / 128, M3 / 128), 256>>>(
        H3, w4T, out, M3, C_, CM_, b4, nullptr, nullptr, nullptr, 0, X1);
}

// round 4
// speedup vs baseline: 3.2183x; 1.7093x over previous
#include <cuda_runtime.h>
#include <math.h>

#define EPSY 0.1f
#define B_  64
#define P_  196
#define C_  768
#define TM_ 384
#define CM_ 3072

// ---------------- scratch ----------------
__device__ float g_H1[(size_t)B_ * C_ * TM_];
__device__ float g_X1[(size_t)B_ * P_ * C_];
__device__ float g_H3[(size_t)B_ * P_ * CM_];
__device__ float g_twT[P_ * TM_];
__device__ float g_w2T[TM_ * P_];
__device__ float g_cwT[C_ * CM_];
__device__ float g_w4T[CM_ * C_];
__device__ float g_twn[TM_];
__device__ float g_cwn[CM_];
__device__ float g_xn1[B_ * C_];
__device__ float g_xn2[B_ * P_];
__device__ float g_scales[2];

__device__ __forceinline__ float f2tf_val(float v) {
    unsigned u;
    asm("cvt.rna.tf32.f32 %0, %1;" : "=r"(u) : "f"(v));
    return __uint_as_float(u);
}

__device__ __forceinline__ unsigned smem_u32(const void* p) {
    return (unsigned)__cvta_generic_to_shared(p);
}

__device__ __forceinline__ void cp16(unsigned dst, const void* src, int bytes) {
    asm volatile("cp.async.ca.shared.global [%0], [%1], 16, %2;\n"
                 :: "r"(dst), "l"(src), "r"(bytes));
}
__device__ __forceinline__ void cp_commit() {
    asm volatile("cp.async.commit_group;\n");
}
__device__ __forceinline__ void cp_wait1() {
    asm volatile("cp.async.wait_group 1;\n");
}

// ---------------- prep kernels (weights pre-rounded to tf32) ----------------
__global__ void transpose_k(const float* __restrict__ in, float* __restrict__ out,
                            int R, int C) {
    __shared__ float tile[32][33];
    int c0 = blockIdx.x * 32, r0 = blockIdx.y * 32;
    int c = c0 + threadIdx.x;
    #pragma unroll
    for (int i = 0; i < 32; i += 8) {
        int r = r0 + threadIdx.y + i;
        if (r < R && c < C) tile[threadIdx.y + i][threadIdx.x] = in[(size_t)r * C + c];
    }
    __syncthreads();
    int oc = r0 + threadIdx.x;
    #pragma unroll
    for (int i = 0; i < 32; i += 8) {
        int orow = c0 + threadIdx.y + i;
        if (orow < C && oc < R)
            out[(size_t)orow * R + oc] = f2tf_val(tile[threadIdx.x][threadIdx.y + i]);
    }
}

__global__ void rownorm_k(const float* __restrict__ in, float* __restrict__ out,
                          int M, int K) {
    int row = blockIdx.x * 8 + (threadIdx.x >> 5);
    int lane = threadIdx.x & 31;
    if (row >= M) return;
    const float* p = in + (size_t)row * K;
    float s = 0.f;
    for (int k = lane; k < K; k += 32) { float v = p[k]; s += v * v; }
    #pragma unroll
    for (int o = 16; o; o >>= 1) s += __shfl_xor_sync(0xffffffffu, s, o);
    if (lane == 0) out[row] = s;
}

__global__ void xnorm_token_k(const float* __restrict__ x, float* __restrict__ out) {
    int idx = blockIdx.x * blockDim.x + threadIdx.x;
    if (idx >= B_ * C_) return;
    int b = idx / C_, c = idx % C_;
    const float* p = x + (size_t)b * P_ * C_ + c;
    float s = 0.f;
    #pragma unroll 4
    for (int k = 0; k < P_; k++) { float v = p[(size_t)k * C_]; s += v * v; }
    out[idx] = s;
}

__global__ void scales_k(const float* __restrict__ ta, const float* __restrict__ ca,
                         float* __restrict__ out) {
    if (threadIdx.x == 0) {
        float bt = (float)((double)TM_ / log((double)TM_ + 1.0));
        float bc = (float)((double)CM_ / log((double)CM_ + 1.0));
        out[0] = powf(sqrtf(bt), ta[0]);
        out[1] = powf(sqrtf(bc), ca[0]);
    }
}

// ---------------- TF32 tensor-core GEMM, cp.async double-buffered ----------------
#define AMODE_ROW  0
#define AMODE_TOKX 1
#define EPI_YAT  0
#define EPI_SCAT 1
#define EPI_ROW  2

__device__ __forceinline__ void mma_tf32(float* c, const unsigned* a, const unsigned* b) {
    asm volatile(
        "mma.sync.aligned.m16n8k8.row.col.f32.tf32.tf32.f32 "
        "{%0,%1,%2,%3}, {%4,%5,%6,%7}, {%8,%9}, {%0,%1,%2,%3};\n"
        : "+f"(c[0]), "+f"(c[1]), "+f"(c[2]), "+f"(c[3])
        : "r"(a[0]), "r"(a[1]), "r"(a[2]), "r"(a[3]), "r"(b[0]), "r"(b[1]));
}

template <int AMODE, int EPI>
__global__ __launch_bounds__(256, 2)
void gemm_tc(const float* __restrict__ A, const float* __restrict__ Bt,
             float* __restrict__ Out, int M, int N, int K,
             const float* __restrict__ bias,
             const float* __restrict__ wn, const float* __restrict__ xn,
             const float* __restrict__ scales, int scale_idx,
             const float* __restrict__ shortcut) {
    constexpr int BM = 128, BN = 128, BK = 16;
    // AMODE_ROW : As[r][k], stride 20 words (80B, 16B-aligned, conflict-free)
    // AMODE_TOKX: As[k][r], stride 136 words
    constexpr int LDA = (AMODE == AMODE_ROW) ? 20 : 136;
    constexpr int ASZ = (AMODE == AMODE_ROW) ? (BM * LDA) : (BK * LDA);
    constexpr int LDB = 136;
    __shared__ __align__(16) unsigned As[2][ASZ];
    __shared__ __align__(16) unsigned Bs[2][BK * LDB];

    const int t    = threadIdx.x;
    const int lane = t & 31;
    const int wid  = t >> 5;
    const int warp_m = wid & 3;
    const int warp_n = wid >> 2;
    const int g  = lane >> 2;
    const int tg = lane & 3;

    const int r0 = blockIdx.y * BM;
    const int n0 = blockIdx.x * BN;

    float acc[2][8][4];
    #pragma unroll
    for (int mt = 0; mt < 2; mt++)
        #pragma unroll
        for (int nt = 0; nt < 8; nt++)
            #pragma unroll
            for (int r = 0; r < 4; r++) acc[mt][nt][r] = 0.f;

    const float* Ablk = A;
    if (AMODE == AMODE_TOKX) {
        int b  = r0 / C_;
        int c0 = r0 % C_;
        Ablk = A + (size_t)b * P_ * C_ + c0;       // (rloc, k) -> Ablk[rloc + k*C_]
    }

    const int ntiles = (K + BK - 1) / BK;

    // ---- async tile loader: 2 A-chunks + 2 B-chunks per thread ----
    auto load_tile = [&](int tile, int buf) {
        const int k0 = tile * BK;
        // A
        #pragma unroll
        for (int i = 0; i < 2; i++) {
            int ch = t + i * 256;                  // 512 chunks
            if (AMODE == AMODE_ROW) {
                int r = ch >> 2, kq = (ch & 3) * 4;
                // K is a multiple of 16 in all ROW-mode uses
                cp16(smem_u32(&As[buf][r * LDA + kq]),
                     A + (size_t)(r0 + r) * K + k0 + kq, 16);
            } else {
                int k = ch >> 5, rq = (ch & 31) * 4;
                int nb = (k0 + k < K) ? 16 : 0;
                const float* src = (nb > 0) ? (Ablk + rq + (size_t)(k0 + k) * C_) : A;
                cp16(smem_u32(&As[buf][k * LDA + rq]), src, nb);
            }
        }
        // B
        #pragma unroll
        for (int i = 0; i < 2; i++) {
            int ch = t + i * 256;
            int k = ch >> 5, nq = (ch & 31) * 4;
            int nb = 0;
            if (k0 + k < K) {
                int rem = (N - (n0 + nq)) * 4;
                nb = rem >= 16 ? 16 : (rem > 0 ? rem : 0);
            }
            const float* src = (nb > 0) ? (Bt + (size_t)(k0 + k) * N + n0 + nq) : Bt;
            cp16(smem_u32(&Bs[buf][k * LDB + nq]), src, nb);
        }
    };

    load_tile(0, 0);
    cp_commit();

    for (int tile = 0; tile < ntiles; tile++) {
        if (tile + 1 < ntiles) load_tile(tile + 1, (tile + 1) & 1);
        cp_commit();
        cp_wait1();
        __syncthreads();

        const unsigned* Asb = As[tile & 1];
        const unsigned* Bsb = Bs[tile & 1];
        #pragma unroll
        for (int ks = 0; ks < 2; ks++) {
            const int kb = ks * 8;
            unsigned a[2][4];
            #pragma unroll
            for (int mt = 0; mt < 2; mt++) {
                int row = warp_m * 32 + mt * 16 + g;
                if (AMODE == AMODE_ROW) {
                    a[mt][0] = Asb[row * LDA + kb + tg];
                    a[mt][1] = Asb[(row + 8) * LDA + kb + tg];
                    a[mt][2] = Asb[row * LDA + kb + tg + 4];
                    a[mt][3] = Asb[(row + 8) * LDA + kb + tg + 4];
                } else {
                    a[mt][0] = Asb[(kb + tg) * LDA + row];
                    a[mt][1] = Asb[(kb + tg) * LDA + row + 8];
                    a[mt][2] = Asb[(kb + tg + 4) * LDA + row];
                    a[mt][3] = Asb[(kb + tg + 4) * LDA + row + 8];
                }
            }
            unsigned b[8][2];
            #pragma unroll
            for (int nt = 0; nt < 8; nt++) {
                int col = warp_n * 64 + nt * 8 + g;
                b[nt][0] = Bsb[(kb + tg) * LDB + col];
                b[nt][1] = Bsb[(kb + tg + 4) * LDB + col];
            }
            #pragma unroll
            for (int mt = 0; mt < 2; mt++)
                #pragma unroll
                for (int nt = 0; nt < 8; nt++)
                    mma_tf32(acc[mt][nt], a[mt], b[nt]);
        }
        __syncthreads();
    }

    // ---- epilogue ----
    const float scale = (EPI == EPI_YAT) ? scales[scale_idx] : 0.f;
    #pragma unroll
    for (int mt = 0; mt < 2; mt++) {
        #pragma unroll
        for (int half = 0; half < 2; half++) {
            const int row = r0 + warp_m * 32 + mt * 16 + g + half * 8;
            const float xnr = (EPI == EPI_YAT) ? xn[row] : 0.f;
            #pragma unroll
            for (int nt = 0; nt < 8; nt++) {
                const int col = n0 + warp_n * 64 + nt * 8 + tg * 2;
                const float d0 = acc[mt][nt][half * 2 + 0];
                const float d1 = acc[mt][nt][half * 2 + 1];
                if (EPI == EPI_YAT) {
                    if (col + 1 < N) {
                        float dot0 = d0 + bias[col];
                        float dot1 = d1 + bias[col + 1];
                        float ds0  = wn[col]     + xnr - 2.f * d0 + EPSY;
                        float ds1  = wn[col + 1] + xnr - 2.f * d1 + EPSY;
                        float2 o = make_float2(scale * dot0 * dot0 / ds0,
                                               scale * dot1 * dot1 / ds1);
                        *(float2*)(Out + (size_t)row * N + col) = o;
                    } else if (col < N) {
                        float dot0 = d0 + bias[col];
                        float ds0  = wn[col] + xnr - 2.f * d0 + EPSY;
                        Out[(size_t)row * N + col] = scale * dot0 * dot0 / ds0;
                    }
                } else if (EPI == EPI_ROW) {
                    if (col + 1 < N) {
                        size_t o = (size_t)row * N + col;
                        float2 v = make_float2(shortcut[o] + d0 + bias[col],
                                               shortcut[o + 1] + d1 + bias[col + 1]);
                        *(float2*)(Out + o) = v;
                    } else if (col < N) {
                        size_t o = (size_t)row * N + col;
                        Out[o] = shortcut[o] + d0 + bias[col];
                    }
                } else { // EPI_SCAT
                    int b = row / C_, c = row % C_;
                    size_t base = (size_t)b * P_ * C_ + c;
                    if (col < N) {
                        size_t o = base + (size_t)col * C_;
                        Out[o] = shortcut[o] + d0 + bias[col];
                    }
                    if (col + 1 < N) {
                        size_t o = base + (size_t)(col + 1) * C_;
                        Out[o] = shortcut[o] + d1 + bias[col + 1];
                    }
                }
            }
        }
    }
}

// ---------------- launch ----------------
extern "C" void kernel_launch(void* const* d_in, const int* in_sizes, int n_in,
                              void* d_out, int out_size) {
    const float* x  = (const float*)d_in[0];
    const float* tw = (const float*)d_in[1];
    const float* tb = (const float*)d_in[2];
    const float* ta = (const float*)d_in[3];
    const float* w2 = (const float*)d_in[4];
    const float* b2 = (const float*)d_in[5];
    const float* cw = (const float*)d_in[6];
    const float* cb = (const float*)d_in[7];
    const float* ca = (const float*)d_in[8];
    const float* w4 = (const float*)d_in[9];
    const float* b4 = (const float*)d_in[10];
    float* out = (float*)d_out;

    float *H1, *X1, *H3, *twT, *w2T, *cwT, *w4T, *twn, *cwn, *xn1, *xn2, *scl;
    cudaGetSymbolAddress((void**)&H1,  g_H1);
    cudaGetSymbolAddress((void**)&X1,  g_X1);
    cudaGetSymbolAddress((void**)&H3,  g_H3);
    cudaGetSymbolAddress((void**)&twT, g_twT);
    cudaGetSymbolAddress((void**)&w2T, g_w2T);
    cudaGetSymbolAddress((void**)&cwT, g_cwT);
    cudaGetSymbolAddress((void**)&w4T, g_w4T);
    cudaGetSymbolAddress((void**)&twn, g_twn);
    cudaGetSymbolAddress((void**)&cwn, g_cwn);
    cudaGetSymbolAddress((void**)&xn1, g_xn1);
    cudaGetSymbolAddress((void**)&xn2, g_xn2);
    cudaGetSymbolAddress((void**)&scl, g_scales);

    dim3 tb32(32, 8);
    transpose_k<<<dim3((P_  + 31) / 32, (TM_ + 31) / 32), tb32>>>(tw, twT, TM_, P_);
    transpose_k<<<dim3((TM_ + 31) / 32, (P_  + 31) / 32), tb32>>>(w2, w2T, P_,  TM_);
    transpose_k<<<dim3((C_  + 31) / 32, (CM_ + 31) / 32), tb32>>>(cw, cwT, CM_, C_);
    transpose_k<<<dim3((CM_ + 31) / 32, (C_  + 31) / 32), tb32>>>(w4, w4T, C_,  CM_);
    rownorm_k<<<(TM_ + 7) / 8, 256>>>(tw, twn, TM_, P_);
    rownorm_k<<<(CM_ + 7) / 8, 256>>>(cw, cwn, CM_, C_);
    xnorm_token_k<<<(B_ * C_ + 255) / 256, 256>>>(x, xn1);
    scales_k<<<1, 32>>>(ta, ca, scl);

    const int M1 = B_ * C_;   // 49152
    const int M3 = B_ * P_;   // 12544

    // GEMM1 + YAT (token): K=196 (zfill to 208)
    gemm_tc<AMODE_TOKX, EPI_YAT><<<dim3(TM_ / 128, M1 / 128), 256>>>(
        x, twT, H1, M1, TM_, P_, tb, twn, xn1, scl, 0, nullptr);

    // GEMM2 + residual scatter: K=384, N=196
    gemm_tc<AMODE_ROW, EPI_SCAT><<<dim3((P_ + 127) / 128, M1 / 128), 256>>>(
        H1, w2T, X1, M1, P_, TM_, b2, nullptr, nullptr, nullptr, 0, x);

    rownorm_k<<<(M3 + 7) / 8, 256>>>(X1, xn2, M3, C_);

    // GEMM3 + YAT (channel): K=768
    gemm_tc<AMODE_ROW, EPI_YAT><<<dim3(CM_ / 128, M3 / 128), 256>>>(
        X1, cwT, H3, M3, CM_, C_, cb, cwn, xn2, scl, 1, nullptr);

    // GEMM4 + residual: K=3072
    gemm_tc<AMODE_ROW, EPI_ROW><<<dim3(C_ / 128, M3 / 128), 256>>>(
        H3, w4T, out, M3, C_, CM_, b4, nullptr, nullptr, nullptr, 0, X1);
}

// round 6
// speedup vs baseline: 5.2030x; 1.6167x over previous
#include <cuda_runtime.h>
#include <cuda_fp16.h>
#include <math.h>
#include <stdint.h>

#define EPSY 0.1f
#define B_  64
#define P_  196
#define C_  768
#define TM_ 384
#define CM_ 3072
#define PPAD 224   // P_ padded to multiple of 32 halves

// ---------------- scratch ----------------
__device__ __half g_xt16[(size_t)B_ * C_ * PPAD];      // x^T fp16, K-padded
__device__ __half g_tw16[TM_ * PPAD];                  // tw fp16, (384, 224)
__device__ __half g_w216[P_ * TM_];                    // w2 fp16, (196, 384)
__device__ __half g_cw16[(size_t)CM_ * C_];            // cw fp16, (3072, 768)
__device__ __half g_w416[(size_t)C_ * CM_];            // w4 fp16, (768, 3072)
__device__ __half g_H116[(size_t)B_ * C_ * TM_];       // H1 fp16 (49152, 384)
__device__ float  g_X1[(size_t)B_ * P_ * C_];          // X1 fp32 (B,P,C)
__device__ __half g_X116[(size_t)B_ * P_ * C_];        // X1 fp16 (12544, 768)
__device__ __half g_H316[(size_t)B_ * P_ * CM_];       // H3 fp16 (12544, 3072)
__device__ float g_twn[TM_];
__device__ float g_cwn[CM_];
__device__ float g_xn1[B_ * C_];
__device__ float g_xn2[B_ * P_];
__device__ float g_scales[2];

__device__ __forceinline__ unsigned smem_u32(const void* p) {
    return (unsigned)__cvta_generic_to_shared(p);
}
__device__ __forceinline__ void cp16(unsigned dst, const void* src, int bytes) {
    asm volatile("cp.async.ca.shared.global [%0], [%1], 16, %2;\n"
                 :: "r"(dst), "l"(src), "r"(bytes));
}
__device__ __forceinline__ void cp_commit() { asm volatile("cp.async.commit_group;\n"); }
__device__ __forceinline__ void cp_wait1() { asm volatile("cp.async.wait_group 1;\n"); }

// ---------------- prep kernels ----------------
// per-batch transpose+convert: x (B,P,C) -> xt16 (B*C, PPAD), zero-padded
__global__ void transpose_cvt_x(const float* __restrict__ x, __half* __restrict__ out) {
    __shared__ float tile[32][33];
    const int b  = blockIdx.z;
    const int c0 = blockIdx.x * 32;     // over C (768: 24 blocks)
    const int p0 = blockIdx.y * 32;     // over PPAD (224: 7 blocks)
    const int tx = threadIdx.x, ty = threadIdx.y;
    #pragma unroll
    for (int i = 0; i < 32; i += 8) {
        int p = p0 + ty + i;
        tile[ty + i][tx] = (p < P_) ? x[(size_t)b * P_ * C_ + (size_t)p * C_ + c0 + tx] : 0.f;
    }
    __syncthreads();
    #pragma unroll
    for (int i = 0; i < 32; i += 8) {
        int c = c0 + ty + i;
        int p = p0 + tx;
        out[((size_t)b * C_ + c) * PPAD + p] = __float2half_rn(tile[tx][ty + i]);
    }
}

// convert + K-pad weights: in (R, Kin) -> out (R, Kout), zero for k >= Kin
__global__ void cvt_pad_w(const float* __restrict__ in, __half* __restrict__ out,
                          int R, int Kin, int Kout) {
    int idx = blockIdx.x * blockDim.x + threadIdx.x;
    if (idx >= R * Kout) return;
    int r = idx / Kout, k = idx % Kout;
    out[idx] = (k < Kin) ? __float2half_rn(in[(size_t)r * Kin + k]) : __half(0.f);
}

__global__ void rownorm_k(const float* __restrict__ in, float* __restrict__ out,
                          int M, int K) {
    int row = blockIdx.x * 8 + (threadIdx.x >> 5);
    int lane = threadIdx.x & 31;
    if (row >= M) return;
    const float* p = in + (size_t)row * K;
    float s = 0.f;
    for (int k = lane; k < K; k += 32) { float v = p[k]; s += v * v; }
    #pragma unroll
    for (int o = 16; o; o >>= 1) s += __shfl_xor_sync(0xffffffffu, s, o);
    if (lane == 0) out[row] = s;
}

__global__ void xnorm_token_k(const float* __restrict__ x, float* __restrict__ out) {
    int idx = blockIdx.x * blockDim.x + threadIdx.x;
    if (idx >= B_ * C_) return;
    int b = idx / C_, c = idx % C_;
    const float* p = x + (size_t)b * P_ * C_ + c;
    float s = 0.f;
    #pragma unroll 4
    for (int k = 0; k < P_; k++) { float v = p[(size_t)k * C_]; s += v * v; }
    out[idx] = s;
}

__global__ void scales_k(const float* __restrict__ ta, const float* __restrict__ ca,
                         float* __restrict__ out) {
    if (threadIdx.x == 0) {
        float bt = (float)((double)TM_ / log((double)TM_ + 1.0));
        float bc = (float)((double)CM_ / log((double)CM_ + 1.0));
        out[0] = powf(sqrtf(bt), ta[0]);
        out[1] = powf(sqrtf(bc), ca[0]);
    }
}

// ================= fp16 tensor-core GEMM, cp.async double-buffered =================
// A: (M x lda) fp16 row-major, K-contiguous. Bw: (N x ldb) fp16 row-major (K-major).
// Computes acc = A * Bw^T over K (padded, multiple of 32).
//
// EPI_YAT16 : Out16[r*N+n] = (half) scale*(acc+bias)^2/(wn+xn-2*acc+EPS)
// EPI_SCATD : X1[b,n,c] = shortcut + acc + bias (fp32)  AND  X116[(b*P+n)*C+c] (fp16)
// EPI_RES32 : Out[r*N+n] = shortcut[r*N+n] + acc + bias[n]  (fp32)
#define EPI_YAT16 0
#define EPI_SCATD 1
#define EPI_RES32 2

__device__ __forceinline__ void mma_f16(float* c, const unsigned* a, const unsigned* b) {
    asm volatile(
        "mma.sync.aligned.m16n8k16.row.col.f32.f16.f16.f32 "
        "{%0,%1,%2,%3}, {%4,%5,%6,%7}, {%8,%9}, {%0,%1,%2,%3};\n"
        : "+f"(c[0]), "+f"(c[1]), "+f"(c[2]), "+f"(c[3])
        : "r"(a[0]), "r"(a[1]), "r"(a[2]), "r"(a[3]), "r"(b[0]), "r"(b[1]));
}

template <int EPI>
__global__ __launch_bounds__(256, 2)
void gemm16(const __half* __restrict__ A, int lda,
            const __half* __restrict__ Bw, int ldb, int NbValid,
            void* __restrict__ OutP, __half* __restrict__ Out16,
            int M, int N, int K,
            const float* __restrict__ bias,
            const float* __restrict__ wn, const float* __restrict__ xn,
            const float* __restrict__ scales, int scale_idx,
            const float* __restrict__ shortcut) {
    constexpr int BM = 128, BN = 128, BK = 32;   // BK in halves
    constexpr int LDK = 40;                      // padded halves per row (20 words)
    __shared__ __align__(16) __half As[2][BM * LDK];
    __shared__ __align__(16) __half Bs[2][BN * LDK];

    const int t    = threadIdx.x;
    const int lane = t & 31;
    const int wid  = t >> 5;
    const int warp_m = wid & 3;
    const int warp_n = wid >> 2;
    const int g  = lane >> 2;
    const int tg = lane & 3;

    const int r0 = blockIdx.y * BM;
    const int n0 = blockIdx.x * BN;

    float acc[2][8][4];
    #pragma unroll
    for (int mt = 0; mt < 2; mt++)
        #pragma unroll
        for (int nt = 0; nt < 8; nt++)
            #pragma unroll
            for (int r = 0; r < 4; r++) acc[mt][nt][r] = 0.f;

    const int ntiles = K / BK;

    auto load_tile = [&](int tile, int buf) {
        const int k0 = tile * BK;
        #pragma unroll
        for (int i = 0; i < 2; i++) {
            int ch = t + i * 256;                // 512 A chunks (128 rows x 4x16B)
            int r = ch >> 2, q = ch & 3;
            cp16(smem_u32(&As[buf][r * LDK + q * 8]),
                 A + (size_t)(r0 + r) * lda + k0 + q * 8, 16);
        }
        #pragma unroll
        for (int i = 0; i < 2; i++) {
            int ch = t + i * 256;
            int r = ch >> 2, q = ch & 3;
            int nb = (n0 + r < NbValid) ? 16 : 0;
            const __half* src = (nb > 0) ? (Bw + (size_t)(n0 + r) * ldb + k0 + q * 8) : Bw;
            cp16(smem_u32(&Bs[buf][r * LDK + q * 8]), src, nb);
        }
    };

    load_tile(0, 0);
    cp_commit();

    for (int tile = 0; tile < ntiles; tile++) {
        if (tile + 1 < ntiles) load_tile(tile + 1, (tile + 1) & 1);
        cp_commit();
        cp_wait1();
        __syncthreads();

        const __half* Asb = As[tile & 1];
        const __half* Bsb = Bs[tile & 1];
        #pragma unroll
        for (int ks = 0; ks < 2; ks++) {
            const int kb = ks * 16;
            unsigned a[2][4];
            #pragma unroll
            for (int mt = 0; mt < 2; mt++) {
                int row = warp_m * 32 + mt * 16 + g;
                a[mt][0] = *(const unsigned*)&Asb[row * LDK + kb + 2 * tg];
                a[mt][1] = *(const unsigned*)&Asb[(row + 8) * LDK + kb + 2 * tg];
                a[mt][2] = *(const unsigned*)&Asb[row * LDK + kb + 2 * tg + 8];
                a[mt][3] = *(const unsigned*)&Asb[(row + 8) * LDK + kb + 2 * tg + 8];
            }
            unsigned b[8][2];
            #pragma unroll
            for (int nt = 0; nt < 8; nt++) {
                int col = warp_n * 64 + nt * 8 + g;
                b[nt][0] = *(const unsigned*)&Bsb[col * LDK + kb + 2 * tg];
                b[nt][1] = *(const unsigned*)&Bsb[col * LDK + kb + 2 * tg + 8];
            }
            #pragma unroll
            for (int mt = 0; mt < 2; mt++)
                #pragma unroll
                for (int nt = 0; nt < 8; nt++)
                    mma_f16(acc[mt][nt], a[mt], b[nt]);
        }
        __syncthreads();
    }

    // ---- epilogue ----
    const float scale = (EPI == EPI_YAT16) ? scales[scale_idx] : 0.f;
    #pragma unroll
    for (int mt = 0; mt < 2; mt++) {
        #pragma unroll
        for (int half = 0; half < 2; half++) {
            const int row = r0 + warp_m * 32 + mt * 16 + g + half * 8;
            const float xnr = (EPI == EPI_YAT16) ? xn[row] : 0.f;
            #pragma unroll
            for (int nt = 0; nt < 8; nt++) {
                const int col = n0 + warp_n * 64 + nt * 8 + tg * 2;
                const float d0 = acc[mt][nt][half * 2 + 0];
                const float d1 = acc[mt][nt][half * 2 + 1];
                if (EPI == EPI_YAT16) {
                    float dot0 = d0 + bias[col];
                    float dot1 = d1 + bias[col + 1];
                    float v0 = scale * dot0 * dot0 / (wn[col]     + xnr - 2.f * d0 + EPSY);
                    float v1 = scale * dot1 * dot1 / (wn[col + 1] + xnr - 2.f * d1 + EPSY);
                    *(__half2*)(Out16 + (size_t)row * N + col) = __floats2half2_rn(v0, v1);
                } else if (EPI == EPI_RES32) {
                    float* Out = (float*)OutP;
                    size_t o = (size_t)row * N + col;
                    float2 v = make_float2(shortcut[o] + d0 + bias[col],
                                           shortcut[o + 1] + d1 + bias[col + 1]);
                    *(float2*)(Out + o) = v;
                } else { // EPI_SCATD: row = b*C + c; write (b, col, c) fp32 + fp16
                    float* Out = (float*)OutP;
                    int b = row / C_, c = row % C_;
                    size_t base = (size_t)b * P_ * C_ + c;
                    if (col < N) {
                        size_t o = base + (size_t)col * C_;
                        float v = shortcut[o] + d0 + bias[col];
                        Out[o] = v;
                        Out16[((size_t)b * P_ + col) * C_ + c] = __float2half_rn(v);
                    }
                    if (col + 1 < N) {
                        size_t o = base + (size_t)(col + 1) * C_;
                        float v = shortcut[o] + d1 + bias[col + 1];
                        Out[o] = v;
                        Out16[((size_t)b * P_ + col + 1) * C_ + c] = __float2half_rn(v);
                    }
                }
            }
        }
    }
}

// ---------------- launch ----------------
extern "C" void kernel_launch(void* const* d_in, const int* in_sizes, int n_in,
                              void* d_out, int out_size) {
    const float* x  = (const float*)d_in[0];
    const float* tw = (const float*)d_in[1];
    const float* tb = (const float*)d_in[2];
    const float* ta = (const float*)d_in[3];
    const float* w2 = (const float*)d_in[4];
    const float* b2 = (const float*)d_in[5];
    const float* cw = (const float*)d_in[6];
    const float* cb = (const float*)d_in[7];
    const float* ca = (const float*)d_in[8];
    const float* w4 = (const float*)d_in[9];
    const float* b4 = (const float*)d_in[10];
    float* out = (float*)d_out;

    __half *xt16, *tw16, *w216, *cw16, *w416, *H116, *X116, *H316;
    float *X1, *twn, *cwn, *xn1, *xn2, *scl;
    cudaGetSymbolAddress((void**)&xt16, g_xt16);
    cudaGetSymbolAddress((void**)&tw16, g_tw16);
    cudaGetSymbolAddress((void**)&w216, g_w216);
    cudaGetSymbolAddress((void**)&cw16, g_cw16);
    cudaGetSymbolAddress((void**)&w416, g_w416);
    cudaGetSymbolAddress((void**)&H116, g_H116);
    cudaGetSymbolAddress((void**)&X1,   g_X1);
    cudaGetSymbolAddress((void**)&X116, g_X116);
    cudaGetSymbolAddress((void**)&H316, g_H316);
    cudaGetSymbolAddress((void**)&twn,  g_twn);
    cudaGetSymbolAddress((void**)&cwn,  g_cwn);
    cudaGetSymbolAddress((void**)&xn1,  g_xn1);
    cudaGetSymbolAddress((void**)&xn2,  g_xn2);
    cudaGetSymbolAddress((void**)&scl,  g_scales);

    // ---- prep ----
    dim3 tb32(32, 8);
    transpose_cvt_x<<<dim3(C_ / 32, PPAD / 32, B_), tb32>>>(x, xt16);
    cvt_pad_w<<<(TM_ * PPAD + 255) / 256, 256>>>(tw, tw16, TM_, P_, PPAD);
    cvt_pad_w<<<(P_ * TM_ + 255) / 256, 256>>>(w2, w216, P_, TM_, TM_);
    cvt_pad_w<<<(CM_ * C_ + 255) / 256, 256>>>(cw, cw16, CM_, C_, C_);
    cvt_pad_w<<<(C_ * CM_ + 255) / 256, 256>>>(w4, w416, C_, CM_, CM_);
    rownorm_k<<<(TM_ + 7) / 8, 256>>>(tw, twn, TM_, P_);
    rownorm_k<<<(CM_ + 7) / 8, 256>>>(cw, cwn, CM_, C_);
    xnorm_token_k<<<(B_ * C_ + 255) / 256, 256>>>(x, xn1);
    scales_k<<<1, 32>>>(ta, ca, scl);

    const int M1 = B_ * C_;   // 49152
    const int M3 = B_ * P_;   // 12544

    // GEMM1 + YAT (token): A=xt16 (M1 x 224), B=tw16 (384 x 224) -> H116 fp16
    gemm16<EPI_YAT16><<<dim3(TM_ / 128, M1 / 128), 256>>>(
        xt16, PPAD, tw16, PPAD, TM_, nullptr, H116,
        M1, TM_, PPAD, tb, twn, xn1, scl, 0, nullptr);

    // GEMM2 + residual scatter: A=H116 (M1 x 384), B=w216 (196 x 384) -> X1 fp32 + X116 fp16
    gemm16<EPI_SCATD><<<dim3(2, M1 / 128), 256>>>(
        H116, TM_, w216, TM_, P_, X1, X116,
        M1, P_, TM_, b2, nullptr, nullptr, nullptr, 0, x);

    rownorm_k<<<(M3 + 7) / 8, 256>>>(X1, xn2, M3, C_);

    // GEMM3 + YAT (channel): A=X116 (M3 x 768), B=cw16 (3072 x 768) -> H316 fp16
    gemm16<EPI_YAT16><<<dim3(CM_ / 128, M3 / 128), 256>>>(
        X116, C_, cw16, C_, CM_, nullptr, H316,
        M3, CM_, C_, cb, cwn, xn2, scl, 1, nullptr);

    // GEMM4 + residual: A=H316 (M3 x 3072), B=w416 (768 x 3072) -> out fp32
    gemm16<EPI_RES32><<<dim3(C_ / 128, M3 / 128), 256>>>(
        H316, CM_, w416, CM_, C_, out, nullptr,
        M3, C_, CM_, b4, nullptr, nullptr, nullptr, 0, X1);
}